// round 5
// baseline (speedup 1.0000x reference)
#include <cuda_runtime.h>
#include <cuda_bf16.h>
#include <stdint.h>
#include <cstdint>
#include <math.h>

#define BB 8
#define CC 128
#define PP 2048
#define HH 4
#define CH 512   // CC*HH

// Scratch (device globals — no allocation allowed)
__device__ __nv_bfloat16 g_q[BB*CH*PP];
__device__ __nv_bfloat16 g_k[BB*CH*PP];
__device__ __nv_bfloat16 g_v[BB*CH*PP];
__device__ __nv_bfloat16 g_att[BB*CH*PP];
__device__ float g_s[CC];
__device__ float g_tb[CC];

__device__ __forceinline__ uint32_t smem_u32(const void* p) {
    return (uint32_t)__cvta_generic_to_shared(p);
}
__device__ __forceinline__ uint32_t pack_bf16(float a, float b) {
    __nv_bfloat162 h = __floats2bfloat162_rn(a, b);
    return *reinterpret_cast<uint32_t*>(&h);
}

#define LDSM_X4(r0,r1,r2,r3,addr) \
    asm volatile("ldmatrix.sync.aligned.m8n8.x4.shared.b16 {%0,%1,%2,%3},[%4];" \
        : "=r"(r0),"=r"(r1),"=r"(r2),"=r"(r3) : "r"(addr))
#define LDSM_X4_T(r0,r1,r2,r3,addr) \
    asm volatile("ldmatrix.sync.aligned.m8n8.x4.trans.shared.b16 {%0,%1,%2,%3},[%4];" \
        : "=r"(r0),"=r"(r1),"=r"(r2),"=r"(r3) : "r"(addr))
#define MMA16816(d,a0,a1,a2,a3,b0,b1) \
    asm volatile("mma.sync.aligned.m16n8k16.row.col.f32.bf16.bf16.f32 " \
        "{%0,%1,%2,%3},{%4,%5,%6,%7},{%8,%9},{%0,%1,%2,%3};" \
        : "+f"(d[0]),"+f"(d[1]),"+f"(d[2]),"+f"(d[3]) \
        : "r"(a0),"r"(a1),"r"(a2),"r"(a3),"r"(b0),"r"(b1))

// ---------------------------------------------------------------------------
// Kernel 1: BatchNorm statistics -> per-channel affine (s, t): xn = x*s + t
// ---------------------------------------------------------------------------
__global__ void bn_stats_kernel(const float* __restrict__ in,
                                const float* __restrict__ gamma,
                                const float* __restrict__ beta) {
    int c = blockIdx.x;
    int tid = threadIdx.x;
    float sum = 0.f, sq = 0.f;
    for (int b = 0; b < BB; b++) {
        const float4* row = (const float4*)(in + (size_t)(b*CC + c)*PP);
        for (int i = tid; i < PP/4; i += 256) {
            float4 v = row[i];
            sum += v.x + v.y + v.z + v.w;
            sq  += v.x*v.x + v.y*v.y + v.z*v.z + v.w*v.w;
        }
    }
    __shared__ float ssum[256], ssq[256];
    ssum[tid] = sum; ssq[tid] = sq;
    __syncthreads();
    for (int o = 128; o > 0; o >>= 1) {
        if (tid < o) { ssum[tid] += ssum[tid+o]; ssq[tid] += ssq[tid+o]; }
        __syncthreads();
    }
    if (tid == 0) {
        const float invN = 1.0f / (BB*PP);
        float mean = ssum[0] * invN;
        float var  = ssq[0] * invN - mean*mean;
        float inv  = rsqrtf(var + 1e-5f);
        float s = gamma[c] * inv;
        g_s[c]  = s;
        g_tb[c] = beta[c] - mean * s;
    }
}

// ---------------------------------------------------------------------------
// Kernel 2: fused QKV projection on tensor cores (bf16 mma.sync).
// Block: 128 out-rows x 128 points, K=128. Grid y: 12 m-tiles (4 per segment
// Q/K/V). A = W (row-major, non-trans ldmatrix), B = Xnorm (trans ldmatrix).
// ---------------------------------------------------------------------------
#define WSTR 136
#define XSTR 136
#define QKV_SMEM ((128*WSTR + 128*XSTR) * 2)

__global__ __launch_bounds__(256, 2) void qkv_mma_kernel(
        const float* __restrict__ Wq, const float* __restrict__ bq,
        const float* __restrict__ Wk, const float* __restrict__ bk,
        const float* __restrict__ Wv, const float* __restrict__ bv,
        const float* __restrict__ in) {
    extern __shared__ char smraw[];
    __nv_bfloat16* Ws = (__nv_bfloat16*)smraw;   // [m=128][k=128]
    __nv_bfloat16* Xs = Ws + 128*WSTR;           // [k=128][p=128]

    int b  = blockIdx.z;
    int mt = blockIdx.y;           // 0..11
    int p0 = blockIdx.x * 128;
    int seg = mt >> 2;
    int m0  = (mt & 3) * 128;
    const float* W; const float* bias; __nv_bfloat16* out; float scale;
    if (seg == 0)      { W = Wq; bias = bq; out = g_q; scale = 0.08838834764831845f; }
    else if (seg == 1) { W = Wk; bias = bk; out = g_k; scale = 1.0f; }
    else               { W = Wv; bias = bv; out = g_v; scale = 1.0f; }

    int t = threadIdx.x;
    // Load W tile [128][128] fp32 -> bf16
    #pragma unroll
    for (int it = 0; it < 16; it++) {
        int idx = t + it*256;
        int row = idx >> 5, col4 = idx & 31;
        float4 w = *(const float4*)(W + (size_t)(m0+row)*CC + col4*4);
        uint2 pk; pk.x = pack_bf16(w.x, w.y); pk.y = pack_bf16(w.z, w.w);
        *(uint2*)(Ws + row*WSTR + col4*4) = pk;
    }
    // Load X tile with BN affine, fp32 -> bf16
    #pragma unroll
    for (int it = 0; it < 16; it++) {
        int idx = t + it*256;
        int c = idx >> 5, p4 = idx & 31;
        float4 x = *(const float4*)(in + (size_t)(b*CC + c)*PP + p0 + p4*4);
        float s = g_s[c], tb = g_tb[c];
        uint2 pk;
        pk.x = pack_bf16(x.x*s + tb, x.y*s + tb);
        pk.y = pack_bf16(x.z*s + tb, x.w*s + tb);
        *(uint2*)(Xs + c*XSTR + p4*4) = pk;
    }
    __syncthreads();

    int w = t >> 5, lane = t & 31;
    int wm = w & 3, wn = w >> 2;   // warp tile: rows wm*32..+31, cols wn*64..+63

    uint32_t aAddr = smem_u32(Ws)
        + (wm*32 + (lane&7) + 8*((lane>>3)&1)) * (WSTR*2)
        + ((lane>>4)&1) * 16;
    uint32_t bAddr = smem_u32(Xs)
        + ((lane&7) + 8*((lane>>3)&1)) * (XSTR*2)
        + ((lane>>4)&1) * 16
        + wn*128;

    float acc[2][8][4];
    #pragma unroll
    for (int i = 0; i < 2; i++)
        #pragma unroll
        for (int j = 0; j < 8; j++)
            acc[i][j][0] = acc[i][j][1] = acc[i][j][2] = acc[i][j][3] = 0.f;

    #pragma unroll
    for (int kk = 0; kk < 8; kk++) {
        uint32_t a[2][4];
        LDSM_X4(a[0][0], a[0][1], a[0][2], a[0][3], aAddr + kk*32);
        LDSM_X4(a[1][0], a[1][1], a[1][2], a[1][3], aAddr + 16*(WSTR*2) + kk*32);
        #pragma unroll
        for (int nb2 = 0; nb2 < 4; nb2++) {
            uint32_t b0, b1, b2, b3;
            LDSM_X4_T(b0, b1, b2, b3, bAddr + kk*16*(XSTR*2) + nb2*32);
            #pragma unroll
            for (int mt2 = 0; mt2 < 2; mt2++) {
                MMA16816(acc[mt2][2*nb2  ], a[mt2][0], a[mt2][1], a[mt2][2], a[mt2][3], b0, b1);
                MMA16816(acc[mt2][2*nb2+1], a[mt2][0], a[mt2][1], a[mt2][2], a[mt2][3], b2, b3);
            }
        }
    }

    // Epilogue: + bias, * scale, bf16 store
    #pragma unroll
    for (int mt2 = 0; mt2 < 2; mt2++) {
        int r0 = m0 + wm*32 + mt2*16 + (lane >> 2);
        float bb0 = (bias[r0] ) * 1.0f;
        float bb1 = (bias[r0+8]) * 1.0f;
        #pragma unroll
        for (int nb = 0; nb < 8; nb++) {
            int n = p0 + wn*64 + nb*8 + (lane&3)*2;
            *(uint32_t*)(out + (size_t)(b*CH + r0  )*PP + n) =
                pack_bf16((acc[mt2][nb][0] + bb0)*scale, (acc[mt2][nb][1] + bb0)*scale);
            *(uint32_t*)(out + (size_t)(b*CH + r0+8)*PP + n) =
                pack_bf16((acc[mt2][nb][2] + bb1)*scale, (acc[mt2][nb][3] + bb1)*scale);
        }
    }
}

// ---------------------------------------------------------------------------
// Kernel 3: flash attention, bf16 mma.sync tensor cores, fp32 softmax/accum.
// Br=128 (8 warps x 16 rows), Bc=64, D=128. x4 ldmatrix everywhere.
// ---------------------------------------------------------------------------
#define QSTR 136   // 128 + 8 pad (bf16 elems)
#define KSTR 72    // 64 + 8 pad
#define FLASH_SMEM ((128*QSTR + 128*KSTR + 128*KSTR) * 2)

__global__ __launch_bounds__(256, 1) void flash_kernel() {
    extern __shared__ char smraw[];
    __nv_bfloat16* Qs = (__nv_bfloat16*)smraw;        // [c=128][i=128]
    __nv_bfloat16* Ks = Qs + 128*QSTR;                // [c=128][j=64]
    __nv_bfloat16* Vs = Ks + 128*KSTR;                // [d=128][j=64]

    int b = blockIdx.z, h = blockIdx.y;
    int i0 = blockIdx.x * 128;
    int t = threadIdx.x;
    int w = t >> 5, lane = t & 31;

    const __nv_bfloat16* qb = g_q + (size_t)b*CH*PP + (size_t)h*PP;
    const __nv_bfloat16* kb = g_k + (size_t)b*CH*PP + (size_t)h*PP;
    const __nv_bfloat16* vb = g_v + (size_t)b*CH*PP + (size_t)h*PP;

    #pragma unroll
    for (int it = 0; it < 8; it++) {
        int idx = t + it*256;
        int c = idx >> 4, u = idx & 15;
        *(uint4*)(Qs + c*QSTR + u*8) =
            *(const uint4*)(qb + (size_t)c*(HH*PP) + i0 + u*8);
    }

    uint32_t qs0 = smem_u32(Qs), ks0 = smem_u32(Ks), vs0 = smem_u32(Vs);
    uint32_t aAddr = qs0 + ((lane&7) + 8*((lane>>4)&1)) * (QSTR*2)
                         + (16*w + 8*((lane>>3)&1)) * 2;
    // K x4.trans: groups 0,1 -> rows c0-7/c8-15 at col j; groups 2,3 -> col j+8
    uint32_t kAddr = ks0 + ((lane&7) + 8*((lane>>3)&1)) * (KSTR*2)
                         + ((lane>>4)&1) * 16;
    // V x4 non-trans: groups 0,1 -> d rows nb*8.. cols j/j+8; groups 2,3 -> d rows +8
    uint32_t vAddr = vs0 + (lane&7) * (KSTR*2) + ((lane>>3)&1) * 16
                         + ((lane>>4)&1) * (8*(KSTR*2));

    float m0 = -1e30f, m1 = -1e30f, l0 = 0.f, l1 = 0.f;
    float O[16][4];
    #pragma unroll
    for (int nb = 0; nb < 16; nb++)
        O[nb][0] = O[nb][1] = O[nb][2] = O[nb][3] = 0.f;

    for (int tile = 0; tile < PP/64; tile++) {
        int j0g = tile * 64;
        __syncthreads();
        #pragma unroll
        for (int it = 0; it < 4; it++) {
            int idx = t + it*256;
            int c = idx >> 3, u = idx & 7;
            *(uint4*)(Ks + c*KSTR + u*8) =
                *(const uint4*)(kb + (size_t)c*(HH*PP) + j0g + u*8);
            *(uint4*)(Vs + c*KSTR + u*8) =
                *(const uint4*)(vb + (size_t)c*(HH*PP) + j0g + u*8);
        }
        __syncthreads();

        // S = Q^T K
        float sv[8][4];
        #pragma unroll
        for (int nb = 0; nb < 8; nb++)
            sv[nb][0] = sv[nb][1] = sv[nb][2] = sv[nb][3] = 0.f;

        #pragma unroll
        for (int kk = 0; kk < 8; kk++) {
            uint32_t a0, a1, a2, a3;
            LDSM_X4_T(a0, a1, a2, a3, aAddr + kk*16*(QSTR*2));
            #pragma unroll
            for (int nb2 = 0; nb2 < 4; nb2++) {
                uint32_t b0, b1, b2, b3;
                LDSM_X4_T(b0, b1, b2, b3, kAddr + kk*16*(KSTR*2) + nb2*32);
                MMA16816(sv[2*nb2  ], a0, a1, a2, a3, b0, b1);
                MMA16816(sv[2*nb2+1], a0, a1, a2, a3, b2, b3);
            }
        }

        // Online softmax
        float rmax0 = -1e30f, rmax1 = -1e30f;
        #pragma unroll
        for (int nb = 0; nb < 8; nb++) {
            rmax0 = fmaxf(rmax0, fmaxf(sv[nb][0], sv[nb][1]));
            rmax1 = fmaxf(rmax1, fmaxf(sv[nb][2], sv[nb][3]));
        }
        rmax0 = fmaxf(rmax0, __shfl_xor_sync(0xffffffffu, rmax0, 1));
        rmax0 = fmaxf(rmax0, __shfl_xor_sync(0xffffffffu, rmax0, 2));
        rmax1 = fmaxf(rmax1, __shfl_xor_sync(0xffffffffu, rmax1, 1));
        rmax1 = fmaxf(rmax1, __shfl_xor_sync(0xffffffffu, rmax1, 2));
        float mn0 = fmaxf(m0, rmax0), mn1 = fmaxf(m1, rmax1);
        float al0 = __expf(m0 - mn0), al1 = __expf(m1 - mn1);
        m0 = mn0; m1 = mn1;
        float rs0 = 0.f, rs1 = 0.f;
        #pragma unroll
        for (int nb = 0; nb < 8; nb++) {
            sv[nb][0] = __expf(sv[nb][0] - mn0);
            sv[nb][1] = __expf(sv[nb][1] - mn0);
            sv[nb][2] = __expf(sv[nb][2] - mn1);
            sv[nb][3] = __expf(sv[nb][3] - mn1);
            rs0 += sv[nb][0] + sv[nb][1];
            rs1 += sv[nb][2] + sv[nb][3];
        }
        rs0 += __shfl_xor_sync(0xffffffffu, rs0, 1);
        rs0 += __shfl_xor_sync(0xffffffffu, rs0, 2);
        rs1 += __shfl_xor_sync(0xffffffffu, rs1, 1);
        rs1 += __shfl_xor_sync(0xffffffffu, rs1, 2);
        l0 = l0*al0 + rs0;
        l1 = l1*al1 + rs1;
        #pragma unroll
        for (int nb = 0; nb < 16; nb++) {
            O[nb][0] *= al0; O[nb][1] *= al0;
            O[nb][2] *= al1; O[nb][3] *= al1;
        }

        uint32_t pa[4][4];
        #pragma unroll
        for (int kbk = 0; kbk < 4; kbk++) {
            pa[kbk][0] = pack_bf16(sv[2*kbk][0],   sv[2*kbk][1]);
            pa[kbk][1] = pack_bf16(sv[2*kbk][2],   sv[2*kbk][3]);
            pa[kbk][2] = pack_bf16(sv[2*kbk+1][0], sv[2*kbk+1][1]);
            pa[kbk][3] = pack_bf16(sv[2*kbk+1][2], sv[2*kbk+1][3]);
        }

        // O += P V^T
        #pragma unroll
        for (int kbk = 0; kbk < 4; kbk++) {
            #pragma unroll
            for (int nb2 = 0; nb2 < 8; nb2++) {
                uint32_t b0, b1, b2, b3;
                LDSM_X4(b0, b1, b2, b3, vAddr + nb2*16*(KSTR*2) + kbk*32);
                MMA16816(O[2*nb2  ], pa[kbk][0], pa[kbk][1], pa[kbk][2], pa[kbk][3], b0, b1);
                MMA16816(O[2*nb2+1], pa[kbk][0], pa[kbk][1], pa[kbk][2], pa[kbk][3], b2, b3);
            }
        }
    }

    // Normalize + store att[b][(d*HH+h)][i] (bf16)
    float inv0 = 1.f / l0, inv1 = 1.f / l1;
    size_t obase = (size_t)b*CH*PP + (size_t)h*PP;
    int irow = i0 + 16*w + (lane >> 2);
    #pragma unroll
    for (int nb = 0; nb < 16; nb++) {
        int d0 = 8*nb + 2*(lane & 3);
        g_att[obase + (size_t)(d0  )*HH*PP + irow    ] = __float2bfloat16(O[nb][0] * inv0);
        g_att[obase + (size_t)(d0+1)*HH*PP + irow    ] = __float2bfloat16(O[nb][1] * inv0);
        g_att[obase + (size_t)(d0  )*HH*PP + irow + 8] = __float2bfloat16(O[nb][2] * inv1);
        g_att[obase + (size_t)(d0+1)*HH*PP + irow + 8] = __float2bfloat16(O[nb][3] * inv1);
    }
}

// ---------------------------------------------------------------------------
// Kernel 4: output projection on tensor cores + bias + residual (fp32 out).
// M=128, K=512 (4 chunks of 128), N=2048 per batch.
// ---------------------------------------------------------------------------
__global__ __launch_bounds__(256, 2) void out_mma_kernel(
        const float* __restrict__ Wo, const float* __restrict__ bo,
        const float* __restrict__ resid, float* __restrict__ out) {
    extern __shared__ char smraw[];
    __nv_bfloat16* Ws = (__nv_bfloat16*)smraw;   // [m=128][k=128]
    __nv_bfloat16* Xs = Ws + 128*WSTR;           // [k=128][p=128]

    int b  = blockIdx.z;
    int p0 = blockIdx.x * 128;
    int t  = threadIdx.x;
    int w = t >> 5, lane = t & 31;
    int wm = w & 3, wn = w >> 2;

    uint32_t aAddr = smem_u32(Ws)
        + (wm*32 + (lane&7) + 8*((lane>>3)&1)) * (WSTR*2)
        + ((lane>>4)&1) * 16;
    uint32_t bAddr = smem_u32(Xs)
        + ((lane&7) + 8*((lane>>3)&1)) * (XSTR*2)
        + ((lane>>4)&1) * 16
        + wn*128;

    float acc[2][8][4];
    #pragma unroll
    for (int i = 0; i < 2; i++)
        #pragma unroll
        for (int j = 0; j < 8; j++)
            acc[i][j][0] = acc[i][j][1] = acc[i][j][2] = acc[i][j][3] = 0.f;

    for (int chunk = 0; chunk < 4; chunk++) {
        __syncthreads();
        // Wo chunk [128][128] fp32 -> bf16
        #pragma unroll
        for (int it = 0; it < 16; it++) {
            int idx = t + it*256;
            int row = idx >> 5, col4 = idx & 31;
            float4 ww = *(const float4*)(Wo + (size_t)row*CH + chunk*128 + col4*4);
            uint2 pk; pk.x = pack_bf16(ww.x, ww.y); pk.y = pack_bf16(ww.z, ww.w);
            *(uint2*)(Ws + row*WSTR + col4*4) = pk;
        }
        // att chunk (already bf16) straight copy
        #pragma unroll
        for (int it = 0; it < 8; it++) {
            int idx = t + it*256;
            int c = idx >> 4, u = idx & 15;
            *(uint4*)(Xs + c*XSTR + u*8) =
                *(const uint4*)(g_att + (size_t)(b*CH + chunk*128 + c)*PP + p0 + u*8);
        }
        __syncthreads();

        #pragma unroll
        for (int kk = 0; kk < 8; kk++) {
            uint32_t a[2][4];
            LDSM_X4(a[0][0], a[0][1], a[0][2], a[0][3], aAddr + kk*32);
            LDSM_X4(a[1][0], a[1][1], a[1][2], a[1][3], aAddr + 16*(WSTR*2) + kk*32);
            #pragma unroll
            for (int nb2 = 0; nb2 < 4; nb2++) {
                uint32_t b0, b1, b2, b3;
                LDSM_X4_T(b0, b1, b2, b3, bAddr + kk*16*(XSTR*2) + nb2*32);
                #pragma unroll
                for (int mt2 = 0; mt2 < 2; mt2++) {
                    MMA16816(acc[mt2][2*nb2  ], a[mt2][0], a[mt2][1], a[mt2][2], a[mt2][3], b0, b1);
                    MMA16816(acc[mt2][2*nb2+1], a[mt2][0], a[mt2][1], a[mt2][2], a[mt2][3], b2, b3);
                }
            }
        }
    }

    // Epilogue: + bias + residual, fp32 store
    #pragma unroll
    for (int mt2 = 0; mt2 < 2; mt2++) {
        int r0 = wm*32 + mt2*16 + (lane >> 2);
        float bb0 = bo[r0], bb1 = bo[r0+8];
        #pragma unroll
        for (int nb = 0; nb < 8; nb++) {
            int n = p0 + wn*64 + nb*8 + (lane&3)*2;
            float2 rv0 = *(const float2*)(resid + (size_t)(b*CC + r0  )*PP + n);
            float2 rv1 = *(const float2*)(resid + (size_t)(b*CC + r0+8)*PP + n);
            float2 o0, o1;
            o0.x = acc[mt2][nb][0] + bb0 + rv0.x;
            o0.y = acc[mt2][nb][1] + bb0 + rv0.y;
            o1.x = acc[mt2][nb][2] + bb1 + rv1.x;
            o1.y = acc[mt2][nb][3] + bb1 + rv1.y;
            *(float2*)(out + (size_t)(b*CC + r0  )*PP + n) = o0;
            *(float2*)(out + (size_t)(b*CC + r0+8)*PP + n) = o1;
        }
    }
}

// ---------------------------------------------------------------------------
extern "C" void kernel_launch(void* const* d_in, const int* in_sizes, int n_in,
                              void* d_out, int out_size) {
    (void)in_sizes; (void)n_in; (void)out_size;
    const float* input = (const float*)d_in[0];
    const float* gamma = (const float*)d_in[1];
    const float* beta  = (const float*)d_in[2];
    const float* Wq = (const float*)d_in[3];
    const float* bq = (const float*)d_in[4];
    const float* Wk = (const float*)d_in[5];
    const float* bk = (const float*)d_in[6];
    const float* Wv = (const float*)d_in[7];
    const float* bv = (const float*)d_in[8];
    const float* Wo = (const float*)d_in[9];
    const float* bo = (const float*)d_in[10];
    float* out = (float*)d_out;

    cudaFuncSetAttribute(qkv_mma_kernel, cudaFuncAttributeMaxDynamicSharedMemorySize, QKV_SMEM);
    cudaFuncSetAttribute(flash_kernel, cudaFuncAttributeMaxDynamicSharedMemorySize, FLASH_SMEM);
    cudaFuncSetAttribute(out_mma_kernel, cudaFuncAttributeMaxDynamicSharedMemorySize, QKV_SMEM);

    bn_stats_kernel<<<128, 256>>>(input, gamma, beta);

    qkv_mma_kernel<<<dim3(16, 12, 8), 256, QKV_SMEM>>>(Wq, bq, Wk, bk, Wv, bv, input);

    flash_kernel<<<dim3(16, 4, 8), 256, FLASH_SMEM>>>();

    out_mma_kernel<<<dim3(16, 1, 8), 256, QKV_SMEM>>>(Wo, bo, input, out);
}

// round 8
// speedup vs baseline: 1.7407x; 1.7407x over previous
#include <cuda_runtime.h>
#include <cuda_bf16.h>
#include <stdint.h>
#include <cstdint>
#include <math.h>

#define BB 8
#define CC 128
#define PP 2048
#define HH 4
#define CH 512   // CC*HH

// Scratch (device globals — no allocation allowed)
__device__ __nv_bfloat16 g_q[BB*CH*PP];
__device__ __nv_bfloat16 g_k[BB*CH*PP];
__device__ __nv_bfloat16 g_v[BB*CH*PP];
__device__ __nv_bfloat16 g_att[BB*CH*PP];
__device__ float g_s[CC];
__device__ float g_tb[CC];

__device__ __forceinline__ uint32_t smem_u32(const void* p) {
    return (uint32_t)__cvta_generic_to_shared(p);
}
__device__ __forceinline__ uint32_t pack_bf16(float a, float b) {
    __nv_bfloat162 h = __floats2bfloat162_rn(a, b);
    return *reinterpret_cast<uint32_t*>(&h);
}

#define LDSM_X4(r0,r1,r2,r3,addr) \
    asm volatile("ldmatrix.sync.aligned.m8n8.x4.shared.b16 {%0,%1,%2,%3},[%4];" \
        : "=r"(r0),"=r"(r1),"=r"(r2),"=r"(r3) : "r"(addr))
#define LDSM_X4_T(r0,r1,r2,r3,addr) \
    asm volatile("ldmatrix.sync.aligned.m8n8.x4.trans.shared.b16 {%0,%1,%2,%3},[%4];" \
        : "=r"(r0),"=r"(r1),"=r"(r2),"=r"(r3) : "r"(addr))
#define MMA16816(d,a0,a1,a2,a3,b0,b1) \
    asm volatile("mma.sync.aligned.m16n8k16.row.col.f32.bf16.bf16.f32 " \
        "{%0,%1,%2,%3},{%4,%5,%6,%7},{%8,%9},{%0,%1,%2,%3};" \
        : "+f"(d[0]),"+f"(d[1]),"+f"(d[2]),"+f"(d[3]) \
        : "r"(a0),"r"(a1),"r"(a2),"r"(a3),"r"(b0),"r"(b1))
#define CP_ASYNC16(dst,src) \
    asm volatile("cp.async.cg.shared.global [%0],[%1],16;" :: "r"(dst),"l"(src))
#define CP_COMMIT() asm volatile("cp.async.commit_group;")
#define CP_WAIT1()  asm volatile("cp.async.wait_group 1;")
#define CP_WAIT0()  asm volatile("cp.async.wait_group 0;")

// ---------------------------------------------------------------------------
// Kernel 1: BatchNorm statistics -> per-channel affine (s, t): xn = x*s + t
// ---------------------------------------------------------------------------
__global__ void bn_stats_kernel(const float* __restrict__ in,
                                const float* __restrict__ gamma,
                                const float* __restrict__ beta) {
    int c = blockIdx.x;
    int tid = threadIdx.x;
    float sum = 0.f, sq = 0.f;
    for (int b = 0; b < BB; b++) {
        const float4* row = (const float4*)(in + (size_t)(b*CC + c)*PP);
        for (int i = tid; i < PP/4; i += 256) {
            float4 v = row[i];
            sum += v.x + v.y + v.z + v.w;
            sq  += v.x*v.x + v.y*v.y + v.z*v.z + v.w*v.w;
        }
    }
    __shared__ float ssum[256], ssq[256];
    ssum[tid] = sum; ssq[tid] = sq;
    __syncthreads();
    for (int o = 128; o > 0; o >>= 1) {
        if (tid < o) { ssum[tid] += ssum[tid+o]; ssq[tid] += ssq[tid+o]; }
        __syncthreads();
    }
    if (tid == 0) {
        const float invN = 1.0f / (BB*PP);
        float mean = ssum[0] * invN;
        float var  = ssq[0] * invN - mean*mean;
        float inv  = rsqrtf(var + 1e-5f);
        float s = gamma[c] * inv;
        g_s[c]  = s;
        g_tb[c] = beta[c] - mean * s;
    }
}

// ---------------------------------------------------------------------------
// Kernel 2: fused QKV projection on tensor cores (bf16 mma.sync).
// ---------------------------------------------------------------------------
#define WSTR 136
#define XSTR 136
#define QKV_SMEM ((128*WSTR + 128*XSTR) * 2)

__global__ __launch_bounds__(256, 2) void qkv_mma_kernel(
        const float* __restrict__ Wq, const float* __restrict__ bq,
        const float* __restrict__ Wk, const float* __restrict__ bk,
        const float* __restrict__ Wv, const float* __restrict__ bv,
        const float* __restrict__ in) {
    extern __shared__ char smraw[];
    __nv_bfloat16* Ws = (__nv_bfloat16*)smraw;   // [m=128][k=128]
    __nv_bfloat16* Xs = Ws + 128*WSTR;           // [k=128][p=128]

    int b  = blockIdx.z;
    int mt = blockIdx.y;           // 0..11
    int p0 = blockIdx.x * 128;
    int seg = mt >> 2;
    int m0  = (mt & 3) * 128;
    const float* W; const float* bias; __nv_bfloat16* out; float scale;
    if (seg == 0)      { W = Wq; bias = bq; out = g_q; scale = 0.08838834764831845f; }
    else if (seg == 1) { W = Wk; bias = bk; out = g_k; scale = 1.0f; }
    else               { W = Wv; bias = bv; out = g_v; scale = 1.0f; }

    int t = threadIdx.x;
    #pragma unroll
    for (int it = 0; it < 16; it++) {
        int idx = t + it*256;
        int row = idx >> 5, col4 = idx & 31;
        float4 w = *(const float4*)(W + (size_t)(m0+row)*CC + col4*4);
        uint2 pk; pk.x = pack_bf16(w.x, w.y); pk.y = pack_bf16(w.z, w.w);
        *(uint2*)(Ws + row*WSTR + col4*4) = pk;
    }
    #pragma unroll
    for (int it = 0; it < 16; it++) {
        int idx = t + it*256;
        int c = idx >> 5, p4 = idx & 31;
        float4 x = *(const float4*)(in + (size_t)(b*CC + c)*PP + p0 + p4*4);
        float s = g_s[c], tb = g_tb[c];
        uint2 pk;
        pk.x = pack_bf16(x.x*s + tb, x.y*s + tb);
        pk.y = pack_bf16(x.z*s + tb, x.w*s + tb);
        *(uint2*)(Xs + c*XSTR + p4*4) = pk;
    }
    __syncthreads();

    int w = t >> 5, lane = t & 31;
    int wm = w & 3, wn = w >> 2;

    uint32_t aAddr = smem_u32(Ws)
        + (wm*32 + (lane&7) + 8*((lane>>3)&1)) * (WSTR*2)
        + ((lane>>4)&1) * 16;
    uint32_t bAddr = smem_u32(Xs)
        + ((lane&7) + 8*((lane>>3)&1)) * (XSTR*2)
        + ((lane>>4)&1) * 16
        + wn*128;

    float acc[2][8][4];
    #pragma unroll
    for (int i = 0; i < 2; i++)
        #pragma unroll
        for (int j = 0; j < 8; j++)
            acc[i][j][0] = acc[i][j][1] = acc[i][j][2] = acc[i][j][3] = 0.f;

    #pragma unroll
    for (int kk = 0; kk < 8; kk++) {
        uint32_t a[2][4];
        LDSM_X4(a[0][0], a[0][1], a[0][2], a[0][3], aAddr + kk*32);
        LDSM_X4(a[1][0], a[1][1], a[1][2], a[1][3], aAddr + 16*(WSTR*2) + kk*32);
        #pragma unroll
        for (int nb2 = 0; nb2 < 4; nb2++) {
            uint32_t b0, b1, b2, b3;
            LDSM_X4_T(b0, b1, b2, b3, bAddr + kk*16*(XSTR*2) + nb2*32);
            #pragma unroll
            for (int mt2 = 0; mt2 < 2; mt2++) {
                MMA16816(acc[mt2][2*nb2  ], a[mt2][0], a[mt2][1], a[mt2][2], a[mt2][3], b0, b1);
                MMA16816(acc[mt2][2*nb2+1], a[mt2][0], a[mt2][1], a[mt2][2], a[mt2][3], b2, b3);
            }
        }
    }

    #pragma unroll
    for (int mt2 = 0; mt2 < 2; mt2++) {
        int r0 = m0 + wm*32 + mt2*16 + (lane >> 2);
        float bb0 = bias[r0];
        float bb1 = bias[r0+8];
        #pragma unroll
        for (int nb = 0; nb < 8; nb++) {
            int n = p0 + wn*64 + nb*8 + (lane&3)*2;
            *(uint32_t*)(out + (size_t)(b*CH + r0  )*PP + n) =
                pack_bf16((acc[mt2][nb][0] + bb0)*scale, (acc[mt2][nb][1] + bb0)*scale);
            *(uint32_t*)(out + (size_t)(b*CH + r0+8)*PP + n) =
                pack_bf16((acc[mt2][nb][2] + bb1)*scale, (acc[mt2][nb][3] + bb1)*scale);
        }
    }
}

// ---------------------------------------------------------------------------
// Kernel 3: flash attention, bf16 mma.sync, fp32 softmax/accum.
// Br=128 (8 warps x 16 rows), Bc=64, D=128. Q frags in registers; K/V tiles
// double-buffered via cp.async (2-stage pipeline).
// ---------------------------------------------------------------------------
#define QSTR 136   // 128 + 8 pad (bf16 elems)
#define KSTR 72    // 64 + 8 pad
#define KVSTAGE (128*KSTR)                 // elems per K (or V) stage
#define FLASH_SMEM ((128*QSTR + 4*KVSTAGE) * 2)
#define NT (PP/64)

__global__ __launch_bounds__(256, 1) void flash_kernel() {
    extern __shared__ char smraw[];
    __nv_bfloat16* Qs = (__nv_bfloat16*)smraw;        // [c=128][i=128]
    __nv_bfloat16* KV = Qs + 128*QSTR;                // stage s: K at s*2*KVSTAGE, V at +KVSTAGE

    int b = blockIdx.z, h = blockIdx.y;
    int i0 = blockIdx.x * 128;
    int t = threadIdx.x;
    int w = t >> 5, lane = t & 31;

    const __nv_bfloat16* qb = g_q + (size_t)b*CH*PP + (size_t)h*PP;
    const __nv_bfloat16* kb = g_k + (size_t)b*CH*PP + (size_t)h*PP;
    const __nv_bfloat16* vb = g_v + (size_t)b*CH*PP + (size_t)h*PP;

    // Per-thread copy indices for K/V tiles: 4 rows of 8 elems each for K and V
    int cpc = t >> 3, cpu = t & 7;          // row base c = cpc + it*32, col u = cpu*8
    uint32_t kvs0 = smem_u32(KV);

    // Issue cp.async for tile 0 (stage 0)
    {
        const __nv_bfloat16* ksrc = kb;
        const __nv_bfloat16* vsrc = vb;
        #pragma unroll
        for (int it = 0; it < 4; it++) {
            int c = cpc + it*32;
            uint32_t kd = kvs0 + (c*KSTR + cpu*8)*2;
            CP_ASYNC16(kd, ksrc + (size_t)c*(HH*PP) + cpu*8);
            CP_ASYNC16(kd + KVSTAGE*2, vsrc + (size_t)c*(HH*PP) + cpu*8);
        }
        CP_COMMIT();
    }

    // Load Q tile [c][i] (overlaps with async copy)
    #pragma unroll
    for (int it = 0; it < 8; it++) {
        int idx = t + it*256;
        int c = idx >> 4, u = idx & 15;
        *(uint4*)(Qs + c*QSTR + u*8) =
            *(const uint4*)(qb + (size_t)c*(HH*PP) + i0 + u*8);
    }
    __syncthreads();

    // Hoist Q fragments into registers (invariant over KV loop)
    uint32_t qa[8][4];
    {
        uint32_t aAddr = smem_u32(Qs) + ((lane&7) + 8*((lane>>4)&1)) * (QSTR*2)
                             + (16*w + 8*((lane>>3)&1)) * 2;
        #pragma unroll
        for (int kk = 0; kk < 8; kk++)
            LDSM_X4_T(qa[kk][0], qa[kk][1], qa[kk][2], qa[kk][3],
                      aAddr + kk*16*(QSTR*2));
    }

    // ldmatrix lane addresses within a stage (stage offset added per tile)
    uint32_t kAddrBase = kvs0 + (((lane&7) + 8*((lane>>3)&1)) * KSTR + ((lane>>4)&1)*8) * 2;
    uint32_t vAddrBase = kvs0 + KVSTAGE*2
        + (((lane&7) + ((lane>>4)&1)*8) * KSTR + ((lane>>3)&1)*8) * 2;

    float m0 = -1e30f, m1 = -1e30f, l0 = 0.f, l1 = 0.f;
    float O[16][4];
    #pragma unroll
    for (int nb = 0; nb < 16; nb++)
        O[nb][0] = O[nb][1] = O[nb][2] = O[nb][3] = 0.f;

    for (int tile = 0; tile < NT; tile++) {
        int stage = tile & 1;
        // Prefetch next tile into the other stage
        if (tile + 1 < NT) {
            int j0n = (tile + 1) * 64;
            uint32_t so = ((tile + 1) & 1) * (2*KVSTAGE*2);
            #pragma unroll
            for (int it = 0; it < 4; it++) {
                int c = cpc + it*32;
                uint32_t kd = kvs0 + so + (c*KSTR + cpu*8)*2;
                CP_ASYNC16(kd, kb + (size_t)c*(HH*PP) + j0n + cpu*8);
                CP_ASYNC16(kd + KVSTAGE*2, vb + (size_t)c*(HH*PP) + j0n + cpu*8);
            }
            CP_COMMIT();
            CP_WAIT1();
        } else {
            CP_WAIT0();
        }
        __syncthreads();

        uint32_t soff = stage * (2*KVSTAGE*2);
        uint32_t kAddr = kAddrBase + soff;
        uint32_t vAddr = vAddrBase + soff;

        // S = Q^T K
        float sv[8][4];
        #pragma unroll
        for (int nb = 0; nb < 8; nb++)
            sv[nb][0] = sv[nb][1] = sv[nb][2] = sv[nb][3] = 0.f;

        #pragma unroll
        for (int kk = 0; kk < 8; kk++) {
            #pragma unroll
            for (int nb2 = 0; nb2 < 4; nb2++) {
                uint32_t b0, b1, b2, b3;
                LDSM_X4_T(b0, b1, b2, b3, kAddr + kk*16*(KSTR*2) + nb2*32);
                MMA16816(sv[2*nb2  ], qa[kk][0], qa[kk][1], qa[kk][2], qa[kk][3], b0, b1);
                MMA16816(sv[2*nb2+1], qa[kk][0], qa[kk][1], qa[kk][2], qa[kk][3], b2, b3);
            }
        }

        // Online softmax
        float rmax0 = -1e30f, rmax1 = -1e30f;
        #pragma unroll
        for (int nb = 0; nb < 8; nb++) {
            rmax0 = fmaxf(rmax0, fmaxf(sv[nb][0], sv[nb][1]));
            rmax1 = fmaxf(rmax1, fmaxf(sv[nb][2], sv[nb][3]));
        }
        rmax0 = fmaxf(rmax0, __shfl_xor_sync(0xffffffffu, rmax0, 1));
        rmax0 = fmaxf(rmax0, __shfl_xor_sync(0xffffffffu, rmax0, 2));
        rmax1 = fmaxf(rmax1, __shfl_xor_sync(0xffffffffu, rmax1, 1));
        rmax1 = fmaxf(rmax1, __shfl_xor_sync(0xffffffffu, rmax1, 2));
        float mn0 = fmaxf(m0, rmax0), mn1 = fmaxf(m1, rmax1);
        float al0 = __expf(m0 - mn0), al1 = __expf(m1 - mn1);
        m0 = mn0; m1 = mn1;
        float rs0 = 0.f, rs1 = 0.f;
        #pragma unroll
        for (int nb = 0; nb < 8; nb++) {
            sv[nb][0] = __expf(sv[nb][0] - mn0);
            sv[nb][1] = __expf(sv[nb][1] - mn0);
            sv[nb][2] = __expf(sv[nb][2] - mn1);
            sv[nb][3] = __expf(sv[nb][3] - mn1);
            rs0 += sv[nb][0] + sv[nb][1];
            rs1 += sv[nb][2] + sv[nb][3];
        }
        rs0 += __shfl_xor_sync(0xffffffffu, rs0, 1);
        rs0 += __shfl_xor_sync(0xffffffffu, rs0, 2);
        rs1 += __shfl_xor_sync(0xffffffffu, rs1, 1);
        rs1 += __shfl_xor_sync(0xffffffffu, rs1, 2);
        l0 = l0*al0 + rs0;
        l1 = l1*al1 + rs1;
        #pragma unroll
        for (int nb = 0; nb < 16; nb++) {
            O[nb][0] *= al0; O[nb][1] *= al0;
            O[nb][2] *= al1; O[nb][3] *= al1;
        }

        uint32_t pa[4][4];
        #pragma unroll
        for (int kbk = 0; kbk < 4; kbk++) {
            pa[kbk][0] = pack_bf16(sv[2*kbk][0],   sv[2*kbk][1]);
            pa[kbk][1] = pack_bf16(sv[2*kbk][2],   sv[2*kbk][3]);
            pa[kbk][2] = pack_bf16(sv[2*kbk+1][0], sv[2*kbk+1][1]);
            pa[kbk][3] = pack_bf16(sv[2*kbk+1][2], sv[2*kbk+1][3]);
        }

        // O += P V^T
        #pragma unroll
        for (int kbk = 0; kbk < 4; kbk++) {
            #pragma unroll
            for (int nb2 = 0; nb2 < 8; nb2++) {
                uint32_t b0, b1, b2, b3;
                LDSM_X4(b0, b1, b2, b3, vAddr + nb2*16*(KSTR*2) + kbk*32);
                MMA16816(O[2*nb2  ], pa[kbk][0], pa[kbk][1], pa[kbk][2], pa[kbk][3], b0, b1);
                MMA16816(O[2*nb2+1], pa[kbk][0], pa[kbk][1], pa[kbk][2], pa[kbk][3], b2, b3);
            }
        }
        __syncthreads();
    }

    // Normalize + store att[b][(d*HH+h)][i] (bf16)
    float inv0 = 1.f / l0, inv1 = 1.f / l1;
    size_t obase = (size_t)b*CH*PP + (size_t)h*PP;
    int irow = i0 + 16*w + (lane >> 2);
    #pragma unroll
    for (int nb = 0; nb < 16; nb++) {
        int d0 = 8*nb + 2*(lane & 3);
        g_att[obase + (size_t)(d0  )*HH*PP + irow    ] = __float2bfloat16(O[nb][0] * inv0);
        g_att[obase + (size_t)(d0+1)*HH*PP + irow    ] = __float2bfloat16(O[nb][1] * inv0);
        g_att[obase + (size_t)(d0  )*HH*PP + irow + 8] = __float2bfloat16(O[nb][2] * inv1);
        g_att[obase + (size_t)(d0+1)*HH*PP + irow + 8] = __float2bfloat16(O[nb][3] * inv1);
    }
}

// ---------------------------------------------------------------------------
// Kernel 4: output projection on tensor cores + bias + residual (fp32 out).
// ---------------------------------------------------------------------------
__global__ __launch_bounds__(256, 2) void out_mma_kernel(
        const float* __restrict__ Wo, const float* __restrict__ bo,
        const float* __restrict__ resid, float* __restrict__ out) {
    extern __shared__ char smraw[];
    __nv_bfloat16* Ws = (__nv_bfloat16*)smraw;   // [m=128][k=128]
    __nv_bfloat16* Xs = Ws + 128*WSTR;           // [k=128][p=128]

    int b  = blockIdx.z;
    int p0 = blockIdx.x * 128;
    int t  = threadIdx.x;
    int w = t >> 5, lane = t & 31;
    int wm = w & 3, wn = w >> 2;

    uint32_t aAddr = smem_u32(Ws)
        + (wm*32 + (lane&7) + 8*((lane>>3)&1)) * (WSTR*2)
        + ((lane>>4)&1) * 16;
    uint32_t bAddr = smem_u32(Xs)
        + ((lane&7) + 8*((lane>>3)&1)) * (XSTR*2)
        + ((lane>>4)&1) * 16
        + wn*128;

    float acc[2][8][4];
    #pragma unroll
    for (int i = 0; i < 2; i++)
        #pragma unroll
        for (int j = 0; j < 8; j++)
            acc[i][j][0] = acc[i][j][1] = acc[i][j][2] = acc[i][j][3] = 0.f;

    for (int chunk = 0; chunk < 4; chunk++) {
        __syncthreads();
        #pragma unroll
        for (int it = 0; it < 16; it++) {
            int idx = t + it*256;
            int row = idx >> 5, col4 = idx & 31;
            float4 ww = *(const float4*)(Wo + (size_t)row*CH + chunk*128 + col4*4);
            uint2 pk; pk.x = pack_bf16(ww.x, ww.y); pk.y = pack_bf16(ww.z, ww.w);
            *(uint2*)(Ws + row*WSTR + col4*4) = pk;
        }
        #pragma unroll
        for (int it = 0; it < 8; it++) {
            int idx = t + it*256;
            int c = idx >> 4, u = idx & 15;
            *(uint4*)(Xs + c*XSTR + u*8) =
                *(const uint4*)(g_att + (size_t)(b*CH + chunk*128 + c)*PP + p0 + u*8);
        }
        __syncthreads();

        #pragma unroll
        for (int kk = 0; kk < 8; kk++) {
            uint32_t a[2][4];
            LDSM_X4(a[0][0], a[0][1], a[0][2], a[0][3], aAddr + kk*32);
            LDSM_X4(a[1][0], a[1][1], a[1][2], a[1][3], aAddr + 16*(WSTR*2) + kk*32);
            #pragma unroll
            for (int nb2 = 0; nb2 < 4; nb2++) {
                uint32_t b0, b1, b2, b3;
                LDSM_X4_T(b0, b1, b2, b3, bAddr + kk*16*(XSTR*2) + nb2*32);
                #pragma unroll
                for (int mt2 = 0; mt2 < 2; mt2++) {
                    MMA16816(acc[mt2][2*nb2  ], a[mt2][0], a[mt2][1], a[mt2][2], a[mt2][3], b0, b1);
                    MMA16816(acc[mt2][2*nb2+1], a[mt2][0], a[mt2][1], a[mt2][2], a[mt2][3], b2, b3);
                }
            }
        }
    }

    #pragma unroll
    for (int mt2 = 0; mt2 < 2; mt2++) {
        int r0 = wm*32 + mt2*16 + (lane >> 2);
        float bb0 = bo[r0], bb1 = bo[r0+8];
        #pragma unroll
        for (int nb = 0; nb < 8; nb++) {
            int n = p0 + wn*64 + nb*8 + (lane&3)*2;
            float2 rv0 = *(const float2*)(resid + (size_t)(b*CC + r0  )*PP + n);
            float2 rv1 = *(const float2*)(resid + (size_t)(b*CC + r0+8)*PP + n);
            float2 o0, o1;
            o0.x = acc[mt2][nb][0] + bb0 + rv0.x;
            o0.y = acc[mt2][nb][1] + bb0 + rv0.y;
            o1.x = acc[mt2][nb][2] + bb1 + rv1.x;
            o1.y = acc[mt2][nb][3] + bb1 + rv1.y;
            *(float2*)(out + (size_t)(b*CC + r0  )*PP + n) = o0;
            *(float2*)(out + (size_t)(b*CC + r0+8)*PP + n) = o1;
        }
    }
}

// ---------------------------------------------------------------------------
extern "C" void kernel_launch(void* const* d_in, const int* in_sizes, int n_in,
                              void* d_out, int out_size) {
    (void)in_sizes; (void)n_in; (void)out_size;
    const float* input = (const float*)d_in[0];
    const float* gamma = (const float*)d_in[1];
    const float* beta  = (const float*)d_in[2];
    const float* Wq = (const float*)d_in[3];
    const float* bq = (const float*)d_in[4];
    const float* Wk = (const float*)d_in[5];
    const float* bk = (const float*)d_in[6];
    const float* Wv = (const float*)d_in[7];
    const float* bv = (const float*)d_in[8];
    const float* Wo = (const float*)d_in[9];
    const float* bo = (const float*)d_in[10];
    float* out = (float*)d_out;

    cudaFuncSetAttribute(qkv_mma_kernel, cudaFuncAttributeMaxDynamicSharedMemorySize, QKV_SMEM);
    cudaFuncSetAttribute(flash_kernel, cudaFuncAttributeMaxDynamicSharedMemorySize, FLASH_SMEM);
    cudaFuncSetAttribute(out_mma_kernel, cudaFuncAttributeMaxDynamicSharedMemorySize, QKV_SMEM);

    bn_stats_kernel<<<128, 256>>>(input, gamma, beta);

    qkv_mma_kernel<<<dim3(16, 12, 8), 256, QKV_SMEM>>>(Wq, bq, Wk, bk, Wv, bv, input);

    flash_kernel<<<dim3(16, 4, 8), 256, FLASH_SMEM>>>();

    out_mma_kernel<<<dim3(16, 1, 8), 256, QKV_SMEM>>>(Wo, bo, input, out);
}

// round 9
// speedup vs baseline: 1.8537x; 1.0649x over previous
#include <cuda_runtime.h>
#include <cuda_bf16.h>
#include <stdint.h>
#include <cstdint>
#include <math.h>

#define BB 8
#define CC 128
#define PP 2048
#define HH 4
#define CH 512   // CC*HH

// Scratch (device globals — no allocation allowed)
__device__ __nv_bfloat16 g_q[BB*CH*PP];
__device__ __nv_bfloat16 g_k[BB*CH*PP];
__device__ __nv_bfloat16 g_v[BB*CH*PP];
__device__ __nv_bfloat16 g_att[BB*CH*PP];
__device__ float g_s[CC];
__device__ float g_tb[CC];

__device__ __forceinline__ uint32_t smem_u32(const void* p) {
    return (uint32_t)__cvta_generic_to_shared(p);
}
__device__ __forceinline__ uint32_t pack_bf16(float a, float b) {
    __nv_bfloat162 h = __floats2bfloat162_rn(a, b);
    return *reinterpret_cast<uint32_t*>(&h);
}

#define LDSM_X4(r0,r1,r2,r3,addr) \
    asm volatile("ldmatrix.sync.aligned.m8n8.x4.shared.b16 {%0,%1,%2,%3},[%4];" \
        : "=r"(r0),"=r"(r1),"=r"(r2),"=r"(r3) : "r"(addr))
#define LDSM_X4_T(r0,r1,r2,r3,addr) \
    asm volatile("ldmatrix.sync.aligned.m8n8.x4.trans.shared.b16 {%0,%1,%2,%3},[%4];" \
        : "=r"(r0),"=r"(r1),"=r"(r2),"=r"(r3) : "r"(addr))
#define MMA16816(d,a0,a1,a2,a3,b0,b1) \
    asm volatile("mma.sync.aligned.m16n8k16.row.col.f32.bf16.bf16.f32 " \
        "{%0,%1,%2,%3},{%4,%5,%6,%7},{%8,%9},{%0,%1,%2,%3};" \
        : "+f"(d[0]),"+f"(d[1]),"+f"(d[2]),"+f"(d[3]) \
        : "r"(a0),"r"(a1),"r"(a2),"r"(a3),"r"(b0),"r"(b1))
#define CP_ASYNC16(dst,src) \
    asm volatile("cp.async.cg.shared.global [%0],[%1],16;" :: "r"(dst),"l"(src))
#define CP_COMMIT() asm volatile("cp.async.commit_group;")
#define CP_WAIT1()  asm volatile("cp.async.wait_group 1;")
#define CP_WAIT0()  asm volatile("cp.async.wait_group 0;")

// ---------------------------------------------------------------------------
// Kernel 1: BatchNorm statistics -> per-channel affine (s, t): xn = x*s + t
// ---------------------------------------------------------------------------
__global__ void bn_stats_kernel(const float* __restrict__ in,
                                const float* __restrict__ gamma,
                                const float* __restrict__ beta) {
    int c = blockIdx.x;
    int tid = threadIdx.x;
    float sum = 0.f, sq = 0.f;
    for (int b = 0; b < BB; b++) {
        const float4* row = (const float4*)(in + (size_t)(b*CC + c)*PP);
        for (int i = tid; i < PP/4; i += 256) {
            float4 v = row[i];
            sum += v.x + v.y + v.z + v.w;
            sq  += v.x*v.x + v.y*v.y + v.z*v.z + v.w*v.w;
        }
    }
    __shared__ float ssum[256], ssq[256];
    ssum[tid] = sum; ssq[tid] = sq;
    __syncthreads();
    for (int o = 128; o > 0; o >>= 1) {
        if (tid < o) { ssum[tid] += ssum[tid+o]; ssq[tid] += ssq[tid+o]; }
        __syncthreads();
    }
    if (tid == 0) {
        const float invN = 1.0f / (BB*PP);
        float mean = ssum[0] * invN;
        float var  = ssq[0] * invN - mean*mean;
        float inv  = rsqrtf(var + 1e-5f);
        float s = gamma[c] * inv;
        g_s[c]  = s;
        g_tb[c] = beta[c] - mean * s;
    }
}

// ---------------------------------------------------------------------------
// Kernel 2: fused QKV projection on tensor cores (bf16 mma.sync).
// ---------------------------------------------------------------------------
#define WSTR 136
#define XSTR 136
#define QKV_SMEM ((128*WSTR + 128*XSTR) * 2)

__global__ __launch_bounds__(256, 2) void qkv_mma_kernel(
        const float* __restrict__ Wq, const float* __restrict__ bq,
        const float* __restrict__ Wk, const float* __restrict__ bk,
        const float* __restrict__ Wv, const float* __restrict__ bv,
        const float* __restrict__ in) {
    extern __shared__ char smraw[];
    __nv_bfloat16* Ws = (__nv_bfloat16*)smraw;   // [m=128][k=128]
    __nv_bfloat16* Xs = Ws + 128*WSTR;           // [k=128][p=128]

    int b  = blockIdx.z;
    int mt = blockIdx.y;           // 0..11
    int p0 = blockIdx.x * 128;
    int seg = mt >> 2;
    int m0  = (mt & 3) * 128;
    const float* W; const float* bias; __nv_bfloat16* out; float scale;
    if (seg == 0)      { W = Wq; bias = bq; out = g_q; scale = 0.08838834764831845f; }
    else if (seg == 1) { W = Wk; bias = bk; out = g_k; scale = 1.0f; }
    else               { W = Wv; bias = bv; out = g_v; scale = 1.0f; }

    int t = threadIdx.x;
    #pragma unroll
    for (int it = 0; it < 16; it++) {
        int idx = t + it*256;
        int row = idx >> 5, col4 = idx & 31;
        float4 w = *(const float4*)(W + (size_t)(m0+row)*CC + col4*4);
        uint2 pk; pk.x = pack_bf16(w.x, w.y); pk.y = pack_bf16(w.z, w.w);
        *(uint2*)(Ws + row*WSTR + col4*4) = pk;
    }
    #pragma unroll
    for (int it = 0; it < 16; it++) {
        int idx = t + it*256;
        int c = idx >> 5, p4 = idx & 31;
        float4 x = *(const float4*)(in + (size_t)(b*CC + c)*PP + p0 + p4*4);
        float s = g_s[c], tb = g_tb[c];
        uint2 pk;
        pk.x = pack_bf16(x.x*s + tb, x.y*s + tb);
        pk.y = pack_bf16(x.z*s + tb, x.w*s + tb);
        *(uint2*)(Xs + c*XSTR + p4*4) = pk;
    }
    __syncthreads();

    int w = t >> 5, lane = t & 31;
    int wm = w & 3, wn = w >> 2;

    uint32_t aAddr = smem_u32(Ws)
        + (wm*32 + (lane&7) + 8*((lane>>3)&1)) * (WSTR*2)
        + ((lane>>4)&1) * 16;
    uint32_t bAddr = smem_u32(Xs)
        + ((lane&7) + 8*((lane>>3)&1)) * (XSTR*2)
        + ((lane>>4)&1) * 16
        + wn*128;

    float acc[2][8][4];
    #pragma unroll
    for (int i = 0; i < 2; i++)
        #pragma unroll
        for (int j = 0; j < 8; j++)
            acc[i][j][0] = acc[i][j][1] = acc[i][j][2] = acc[i][j][3] = 0.f;

    #pragma unroll
    for (int kk = 0; kk < 8; kk++) {
        uint32_t a[2][4];
        LDSM_X4(a[0][0], a[0][1], a[0][2], a[0][3], aAddr + kk*32);
        LDSM_X4(a[1][0], a[1][1], a[1][2], a[1][3], aAddr + 16*(WSTR*2) + kk*32);
        #pragma unroll
        for (int nb2 = 0; nb2 < 4; nb2++) {
            uint32_t b0, b1, b2, b3;
            LDSM_X4_T(b0, b1, b2, b3, bAddr + kk*16*(XSTR*2) + nb2*32);
            #pragma unroll
            for (int mt2 = 0; mt2 < 2; mt2++) {
                MMA16816(acc[mt2][2*nb2  ], a[mt2][0], a[mt2][1], a[mt2][2], a[mt2][3], b0, b1);
                MMA16816(acc[mt2][2*nb2+1], a[mt2][0], a[mt2][1], a[mt2][2], a[mt2][3], b2, b3);
            }
        }
    }

    #pragma unroll
    for (int mt2 = 0; mt2 < 2; mt2++) {
        int r0 = m0 + wm*32 + mt2*16 + (lane >> 2);
        float bb0 = bias[r0];
        float bb1 = bias[r0+8];
        #pragma unroll
        for (int nb = 0; nb < 8; nb++) {
            int n = p0 + wn*64 + nb*8 + (lane&3)*2;
            *(uint32_t*)(out + (size_t)(b*CH + r0  )*PP + n) =
                pack_bf16((acc[mt2][nb][0] + bb0)*scale, (acc[mt2][nb][1] + bb0)*scale);
            *(uint32_t*)(out + (size_t)(b*CH + r0+8)*PP + n) =
                pack_bf16((acc[mt2][nb][2] + bb1)*scale, (acc[mt2][nb][3] + bb1)*scale);
        }
    }
}

// ---------------------------------------------------------------------------
// Kernel 3: flash attention, bf16 mma.sync, fp32 softmax/accum.
// Br=64 (4 warps x 16 rows), Bc=64, D=128, 128 threads, 2 CTAs/SM.
// Independent CTAs overlap softmax (MUFU/shuffle) with the other CTA's MMAs.
// K/V double-buffered via cp.async; Q fragments hoisted to registers.
// ---------------------------------------------------------------------------
#define QSTR 72    // 64 + 8 pad (bf16 elems)
#define KSTR 72    // 64 + 8 pad
#define KVSTAGE (128*KSTR)                 // elems per K (or V) stage
#define FLASH_SMEM ((128*QSTR + 4*KVSTAGE) * 2)
#define NT (PP/64)

__global__ __launch_bounds__(128, 2) void flash_kernel() {
    extern __shared__ char smraw[];
    __nv_bfloat16* Qs = (__nv_bfloat16*)smraw;        // [c=128][i=64]
    __nv_bfloat16* KV = Qs + 128*QSTR;                // stage s: K at s*2*KVSTAGE, V at +KVSTAGE

    int b = blockIdx.z, h = blockIdx.y;
    int i0 = blockIdx.x * 64;
    int t = threadIdx.x;
    int w = t >> 5, lane = t & 31;

    const __nv_bfloat16* qb = g_q + (size_t)b*CH*PP + (size_t)h*PP;
    const __nv_bfloat16* kb = g_k + (size_t)b*CH*PP + (size_t)h*PP;
    const __nv_bfloat16* vb = g_v + (size_t)b*CH*PP + (size_t)h*PP;

    // Per-thread copy indices: 128 threads; 8 iters x (1 K + 1 V) 16B each
    int cpc = t >> 3, cpu = t & 7;          // row base c = cpc + it*16
    uint32_t kvs0 = smem_u32(KV);

    // Issue cp.async for tile 0 (stage 0)
    #pragma unroll
    for (int it = 0; it < 8; it++) {
        int c = cpc + it*16;
        uint32_t kd = kvs0 + (c*KSTR + cpu*8)*2;
        CP_ASYNC16(kd, kb + (size_t)c*(HH*PP) + cpu*8);
        CP_ASYNC16(kd + KVSTAGE*2, vb + (size_t)c*(HH*PP) + cpu*8);
    }
    CP_COMMIT();

    // Load Q tile [c=128][i=64] (overlaps with async copy)
    #pragma unroll
    for (int it = 0; it < 8; it++) {
        int idx = t + it*128;
        int c = idx >> 3, u = idx & 7;
        *(uint4*)(Qs + c*QSTR + u*8) =
            *(const uint4*)(qb + (size_t)c*(HH*PP) + i0 + u*8);
    }
    __syncthreads();

    // Hoist Q fragments into registers (invariant over KV loop)
    uint32_t qa[8][4];
    {
        uint32_t aAddr = smem_u32(Qs) + ((lane&7) + 8*((lane>>4)&1)) * (QSTR*2)
                             + (16*w + 8*((lane>>3)&1)) * 2;
        #pragma unroll
        for (int kk = 0; kk < 8; kk++)
            LDSM_X4_T(qa[kk][0], qa[kk][1], qa[kk][2], qa[kk][3],
                      aAddr + kk*16*(QSTR*2));
    }

    uint32_t kAddrBase = kvs0 + (((lane&7) + 8*((lane>>3)&1)) * KSTR + ((lane>>4)&1)*8) * 2;
    uint32_t vAddrBase = kvs0 + KVSTAGE*2
        + (((lane&7) + ((lane>>4)&1)*8) * KSTR + ((lane>>3)&1)*8) * 2;

    float m0 = -1e30f, m1 = -1e30f, l0 = 0.f, l1 = 0.f;
    float O[16][4];
    #pragma unroll
    for (int nb = 0; nb < 16; nb++)
        O[nb][0] = O[nb][1] = O[nb][2] = O[nb][3] = 0.f;

    for (int tile = 0; tile < NT; tile++) {
        int stage = tile & 1;
        if (tile + 1 < NT) {
            int j0n = (tile + 1) * 64;
            uint32_t so = ((tile + 1) & 1) * (2*KVSTAGE*2);
            #pragma unroll
            for (int it = 0; it < 8; it++) {
                int c = cpc + it*16;
                uint32_t kd = kvs0 + so + (c*KSTR + cpu*8)*2;
                CP_ASYNC16(kd, kb + (size_t)c*(HH*PP) + j0n + cpu*8);
                CP_ASYNC16(kd + KVSTAGE*2, vb + (size_t)c*(HH*PP) + j0n + cpu*8);
            }
            CP_COMMIT();
            CP_WAIT1();
        } else {
            CP_WAIT0();
        }
        __syncthreads();

        uint32_t soff = stage * (2*KVSTAGE*2);
        uint32_t kAddr = kAddrBase + soff;
        uint32_t vAddr = vAddrBase + soff;

        // S = Q^T K
        float sv[8][4];
        #pragma unroll
        for (int nb = 0; nb < 8; nb++)
            sv[nb][0] = sv[nb][1] = sv[nb][2] = sv[nb][3] = 0.f;

        #pragma unroll
        for (int kk = 0; kk < 8; kk++) {
            #pragma unroll
            for (int nb2 = 0; nb2 < 4; nb2++) {
                uint32_t b0, b1, b2, b3;
                LDSM_X4_T(b0, b1, b2, b3, kAddr + kk*16*(KSTR*2) + nb2*32);
                MMA16816(sv[2*nb2  ], qa[kk][0], qa[kk][1], qa[kk][2], qa[kk][3], b0, b1);
                MMA16816(sv[2*nb2+1], qa[kk][0], qa[kk][1], qa[kk][2], qa[kk][3], b2, b3);
            }
        }

        // Online softmax
        float rmax0 = -1e30f, rmax1 = -1e30f;
        #pragma unroll
        for (int nb = 0; nb < 8; nb++) {
            rmax0 = fmaxf(rmax0, fmaxf(sv[nb][0], sv[nb][1]));
            rmax1 = fmaxf(rmax1, fmaxf(sv[nb][2], sv[nb][3]));
        }
        rmax0 = fmaxf(rmax0, __shfl_xor_sync(0xffffffffu, rmax0, 1));
        rmax0 = fmaxf(rmax0, __shfl_xor_sync(0xffffffffu, rmax0, 2));
        rmax1 = fmaxf(rmax1, __shfl_xor_sync(0xffffffffu, rmax1, 1));
        rmax1 = fmaxf(rmax1, __shfl_xor_sync(0xffffffffu, rmax1, 2));
        float mn0 = fmaxf(m0, rmax0), mn1 = fmaxf(m1, rmax1);
        float al0 = __expf(m0 - mn0), al1 = __expf(m1 - mn1);
        m0 = mn0; m1 = mn1;
        float rs0 = 0.f, rs1 = 0.f;
        #pragma unroll
        for (int nb = 0; nb < 8; nb++) {
            sv[nb][0] = __expf(sv[nb][0] - mn0);
            sv[nb][1] = __expf(sv[nb][1] - mn0);
            sv[nb][2] = __expf(sv[nb][2] - mn1);
            sv[nb][3] = __expf(sv[nb][3] - mn1);
            rs0 += sv[nb][0] + sv[nb][1];
            rs1 += sv[nb][2] + sv[nb][3];
        }
        rs0 += __shfl_xor_sync(0xffffffffu, rs0, 1);
        rs0 += __shfl_xor_sync(0xffffffffu, rs0, 2);
        rs1 += __shfl_xor_sync(0xffffffffu, rs1, 1);
        rs1 += __shfl_xor_sync(0xffffffffu, rs1, 2);
        l0 = l0*al0 + rs0;
        l1 = l1*al1 + rs1;
        #pragma unroll
        for (int nb = 0; nb < 16; nb++) {
            O[nb][0] *= al0; O[nb][1] *= al0;
            O[nb][2] *= al1; O[nb][3] *= al1;
        }

        uint32_t pa[4][4];
        #pragma unroll
        for (int kbk = 0; kbk < 4; kbk++) {
            pa[kbk][0] = pack_bf16(sv[2*kbk][0],   sv[2*kbk][1]);
            pa[kbk][1] = pack_bf16(sv[2*kbk][2],   sv[2*kbk][3]);
            pa[kbk][2] = pack_bf16(sv[2*kbk+1][0], sv[2*kbk+1][1]);
            pa[kbk][3] = pack_bf16(sv[2*kbk+1][2], sv[2*kbk+1][3]);
        }

        // O += P V^T
        #pragma unroll
        for (int kbk = 0; kbk < 4; kbk++) {
            #pragma unroll
            for (int nb2 = 0; nb2 < 8; nb2++) {
                uint32_t b0, b1, b2, b3;
                LDSM_X4(b0, b1, b2, b3, vAddr + nb2*16*(KSTR*2) + kbk*32);
                MMA16816(O[2*nb2  ], pa[kbk][0], pa[kbk][1], pa[kbk][2], pa[kbk][3], b0, b1);
                MMA16816(O[2*nb2+1], pa[kbk][0], pa[kbk][1], pa[kbk][2], pa[kbk][3], b2, b3);
            }
        }
        __syncthreads();
    }

    // Normalize + store att[b][(d*HH+h)][i] (bf16)
    float inv0 = 1.f / l0, inv1 = 1.f / l1;
    size_t obase = (size_t)b*CH*PP + (size_t)h*PP;
    int irow = i0 + 16*w + (lane >> 2);
    #pragma unroll
    for (int nb = 0; nb < 16; nb++) {
        int d0 = 8*nb + 2*(lane & 3);
        g_att[obase + (size_t)(d0  )*HH*PP + irow    ] = __float2bfloat16(O[nb][0] * inv0);
        g_att[obase + (size_t)(d0+1)*HH*PP + irow    ] = __float2bfloat16(O[nb][1] * inv0);
        g_att[obase + (size_t)(d0  )*HH*PP + irow + 8] = __float2bfloat16(O[nb][2] * inv1);
        g_att[obase + (size_t)(d0+1)*HH*PP + irow + 8] = __float2bfloat16(O[nb][3] * inv1);
    }
}

// ---------------------------------------------------------------------------
// Kernel 4: output projection on tensor cores + bias + residual (fp32 out).
// Tile M=128 x N=64 -> grid 32x8 = 256 CTAs for latency hiding.
// ---------------------------------------------------------------------------
#define X2STR 72
#define OUT_SMEM ((128*WSTR + 128*X2STR) * 2)

__global__ __launch_bounds__(256, 2) void out_mma_kernel(
        const float* __restrict__ Wo, const float* __restrict__ bo,
        const float* __restrict__ resid, float* __restrict__ out) {
    extern __shared__ char smraw[];
    __nv_bfloat16* Ws = (__nv_bfloat16*)smraw;   // [m=128][k=128]
    __nv_bfloat16* Xs = Ws + 128*WSTR;           // [k=128][p=64]

    int b  = blockIdx.z;
    int p0 = blockIdx.x * 64;
    int t  = threadIdx.x;
    int w = t >> 5, lane = t & 31;
    int wm = w & 3, wn = w >> 2;   // warp: rows wm*32..+31, cols wn*32..+31

    uint32_t aAddr = smem_u32(Ws)
        + (wm*32 + (lane&7) + 8*((lane>>3)&1)) * (WSTR*2)
        + ((lane>>4)&1) * 16;
    uint32_t bAddr = smem_u32(Xs)
        + ((lane&7) + 8*((lane>>3)&1)) * (X2STR*2)
        + ((lane>>4)&1) * 16
        + wn*64;

    float acc[2][4][4];
    #pragma unroll
    for (int i = 0; i < 2; i++)
        #pragma unroll
        for (int j = 0; j < 4; j++)
            acc[i][j][0] = acc[i][j][1] = acc[i][j][2] = acc[i][j][3] = 0.f;

    for (int chunk = 0; chunk < 4; chunk++) {
        __syncthreads();
        // Wo chunk [128][128] fp32 -> bf16
        #pragma unroll
        for (int it = 0; it < 16; it++) {
            int idx = t + it*256;
            int row = idx >> 5, col4 = idx & 31;
            float4 ww = *(const float4*)(Wo + (size_t)row*CH + chunk*128 + col4*4);
            uint2 pk; pk.x = pack_bf16(ww.x, ww.y); pk.y = pack_bf16(ww.z, ww.w);
            *(uint2*)(Ws + row*WSTR + col4*4) = pk;
        }
        // att chunk [128][64] (already bf16) straight copy
        #pragma unroll
        for (int it = 0; it < 4; it++) {
            int idx = t + it*256;
            int c = idx >> 3, u = idx & 7;
            *(uint4*)(Xs + c*X2STR + u*8) =
                *(const uint4*)(g_att + (size_t)(b*CH + chunk*128 + c)*PP + p0 + u*8);
        }
        __syncthreads();

        #pragma unroll
        for (int kk = 0; kk < 8; kk++) {
            uint32_t a[2][4];
            LDSM_X4(a[0][0], a[0][1], a[0][2], a[0][3], aAddr + kk*32);
            LDSM_X4(a[1][0], a[1][1], a[1][2], a[1][3], aAddr + 16*(WSTR*2) + kk*32);
            #pragma unroll
            for (int nb2 = 0; nb2 < 2; nb2++) {
                uint32_t b0, b1, b2, b3;
                LDSM_X4_T(b0, b1, b2, b3, bAddr + kk*16*(X2STR*2) + nb2*32);
                #pragma unroll
                for (int mt2 = 0; mt2 < 2; mt2++) {
                    MMA16816(acc[mt2][2*nb2  ], a[mt2][0], a[mt2][1], a[mt2][2], a[mt2][3], b0, b1);
                    MMA16816(acc[mt2][2*nb2+1], a[mt2][0], a[mt2][1], a[mt2][2], a[mt2][3], b2, b3);
                }
            }
        }
    }

    #pragma unroll
    for (int mt2 = 0; mt2 < 2; mt2++) {
        int r0 = wm*32 + mt2*16 + (lane >> 2);
        float bb0 = bo[r0], bb1 = bo[r0+8];
        #pragma unroll
        for (int nb = 0; nb < 4; nb++) {
            int n = p0 + wn*32 + nb*8 + (lane&3)*2;
            float2 rv0 = *(const float2*)(resid + (size_t)(b*CC + r0  )*PP + n);
            float2 rv1 = *(const float2*)(resid + (size_t)(b*CC + r0+8)*PP + n);
            float2 o0, o1;
            o0.x = acc[mt2][nb][0] + bb0 + rv0.x;
            o0.y = acc[mt2][nb][1] + bb0 + rv0.y;
            o1.x = acc[mt2][nb][2] + bb1 + rv1.x;
            o1.y = acc[mt2][nb][3] + bb1 + rv1.y;
            *(float2*)(out + (size_t)(b*CC + r0  )*PP + n) = o0;
            *(float2*)(out + (size_t)(b*CC + r0+8)*PP + n) = o1;
        }
    }
}

// ---------------------------------------------------------------------------
extern "C" void kernel_launch(void* const* d_in, const int* in_sizes, int n_in,
                              void* d_out, int out_size) {
    (void)in_sizes; (void)n_in; (void)out_size;
    const float* input = (const float*)d_in[0];
    const float* gamma = (const float*)d_in[1];
    const float* beta  = (const float*)d_in[2];
    const float* Wq = (const float*)d_in[3];
    const float* bq = (const float*)d_in[4];
    const float* Wk = (const float*)d_in[5];
    const float* bk = (const float*)d_in[6];
    const float* Wv = (const float*)d_in[7];
    const float* bv = (const float*)d_in[8];
    const float* Wo = (const float*)d_in[9];
    const float* bo = (const float*)d_in[10];
    float* out = (float*)d_out;

    cudaFuncSetAttribute(qkv_mma_kernel, cudaFuncAttributeMaxDynamicSharedMemorySize, QKV_SMEM);
    cudaFuncSetAttribute(flash_kernel, cudaFuncAttributeMaxDynamicSharedMemorySize, FLASH_SMEM);
    cudaFuncSetAttribute(out_mma_kernel, cudaFuncAttributeMaxDynamicSharedMemorySize, OUT_SMEM);

    bn_stats_kernel<<<128, 256>>>(input, gamma, beta);

    qkv_mma_kernel<<<dim3(16, 12, 8), 256, QKV_SMEM>>>(Wq, bq, Wk, bk, Wv, bv, input);

    flash_kernel<<<dim3(32, 4, 8), 128, FLASH_SMEM>>>();

    out_mma_kernel<<<dim3(32, 1, 8), 256, OUT_SMEM>>>(Wo, bo, input, out);
}